// round 1
// baseline (speedup 1.0000x reference)
#include <cuda_runtime.h>
#include <math.h>

#define BB 4
#define LL 2048
#define KK 30
#define HID 128
#define NHD 4
#define NLAY 3
#define NNODE (BB*LL)        /* 8192  */
#define NE (NNODE*KK)        /* 245760 */
#define EPSX 1e-6f

// ---------------- scratch (static device globals; no allocation) ----------
__device__ float g_hV[NNODE*HID];          // 4 MB   node features (in-place updated)
__device__ float g_Q[NNODE*HID];           // 4 MB   Q projection per layer
__device__ float g_hE[NE*HID];             // 126 MB edge features (in-place updated)
__device__ float g_Vh[NE*HID];             // 126 MB V-head values per layer
__device__ float g_logits[NNODE*NHD*KK];   // 3.9 MB attention logits

// ---------------- packed f32x2 FMA (2x FFMA throughput on sm_103a) --------
__device__ __forceinline__ float2 ffma2(float2 d, float2 a, float2 b) {
    unsigned long long du = *reinterpret_cast<unsigned long long*>(&d);
    unsigned long long au = *reinterpret_cast<unsigned long long*>(&a);
    unsigned long long bu = *reinterpret_cast<unsigned long long*>(&b);
    asm("fma.rn.f32x2 %0, %1, %2, %0;" : "+l"(du) : "l"(au), "l"(bu));
    return *reinterpret_cast<float2*>(&du);
}

// stage a 128x128 fp32 matrix into smem (row-major), coalesced float4
__device__ __forceinline__ void stage_mat128(float* ws, const float* __restrict__ W,
                                             int t, int nthreads) {
    for (int i = t; i < (128*128)/4; i += nthreads)
        reinterpret_cast<float4*>(ws)[i] = reinterpret_cast<const float4*>(W)[i];
}

// core tile GEMM: acc[r][p] += a_s[n0+r][j] * w_s[j][c0 + 2p + {0,1}]
// a_s row-major [rows][128], w_s row-major [128][128]
__device__ __forceinline__ void tile_fma(const float* a_s, const float* w_s,
                                         int n0, int c0, float2 acc[4][2]) {
    #pragma unroll 8
    for (int j = 0; j < 128; ++j) {
        float2 w0 = *reinterpret_cast<const float2*>(&w_s[j*128 + c0]);
        float2 w1 = *reinterpret_cast<const float2*>(&w_s[j*128 + c0 + 2]);
        #pragma unroll
        for (int r = 0; r < 4; ++r) {
            float a = a_s[(n0 + r)*128 + j];
            float2 a2 = make_float2(a, a);
            acc[r][0] = ffma2(acc[r][0], a2, w0);
            acc[r][1] = ffma2(acc[r][1], a2, w1);
        }
    }
}

// =====================================================================
// Kernel: out[r,:] = in[r,:] @ W(128x128) (+ bias). 64 rows / CTA.
// =====================================================================
__global__ __launch_bounds__(512) void k_rowgemm(const float* __restrict__ in,
                                                 const float* __restrict__ W,
                                                 const float* __restrict__ bias,
                                                 float* __restrict__ out) {
    extern __shared__ float sm[];
    float* w_s = sm;              // 128*128
    float* a_s = sm + 128*128;    // 64*128
    int t = threadIdx.x, tx = t & 31, ty = t >> 5;
    int base = blockIdx.x * 64;
    int cs = tx * 4;

    stage_mat128(w_s, W, t, 512);
    for (int r = ty; r < 64; r += 16)
        *reinterpret_cast<float4*>(&a_s[r*128 + cs]) =
            *reinterpret_cast<const float4*>(&in[(base + r)*128 + cs]);
    __syncthreads();

    float2 acc[4][2] = {};
    int n0 = ty * 4, c0 = tx * 4;
    tile_fma(a_s, w_s, n0, c0, acc);

    float4 bv = make_float4(0.f, 0.f, 0.f, 0.f);
    if (bias) bv = *reinterpret_cast<const float4*>(&bias[c0]);
    #pragma unroll
    for (int r = 0; r < 4; ++r) {
        float4 o;
        o.x = acc[r][0].x + bv.x; o.y = acc[r][0].y + bv.y;
        o.z = acc[r][1].x + bv.z; o.w = acc[r][1].y + bv.w;
        *reinterpret_cast<float4*>(&out[(base + n0 + r)*128 + c0]) = o;
    }
}

// =====================================================================
// Kernel: per edge row e=(b,l,k):
//   k1 = hE[e] @ Wk1 ; k2 = hV[gather] @ Wk2 ; Vh[e] = [hE,hKV] @ Wv
//   logits[node,h,k] = sum_d Q[node]*k1*k2 / 32
// =====================================================================
__global__ __launch_bounds__(512) void k_logits_vh(const int* __restrict__ E_idx,
                                                   const float* __restrict__ Wk1,
                                                   const float* __restrict__ Wk2,
                                                   const float* __restrict__ Wv) {
    extern __shared__ float sm[];
    float* w_s = sm;
    float* a_s = sm + 128*128;
    __shared__ int grow_s[64];
    int t = threadIdx.x, tx = t & 31, ty = t >> 5;
    int n0 = ty * 4, c0 = tx * 4, cs = tx * 4;
    int base = blockIdx.x * 64;

    if (t < 64) {
        int e = base + t;
        int b = e / (LL * KK);
        grow_s[t] = b * LL + E_idx[e];
    }

    float2 acc1[4][2] = {}, acc2[4][2] = {}, accv[4][2] = {};

    // ---- phase A: a = hE rows (contiguous) ----
    for (int r = ty; r < 64; r += 16)
        *reinterpret_cast<float4*>(&a_s[r*128 + cs]) =
            *reinterpret_cast<const float4*>(&g_hE[(base + r)*128 + cs]);
    stage_mat128(w_s, Wk1, t, 512);
    __syncthreads();
    tile_fma(a_s, w_s, n0, c0, acc1);
    __syncthreads();
    stage_mat128(w_s, Wv, t, 512);            // Wv rows [0:128)
    __syncthreads();
    tile_fma(a_s, w_s, n0, c0, accv);
    __syncthreads();

    // ---- phase B: a = gathered hV rows ----
    for (int r = ty; r < 64; r += 16)
        *reinterpret_cast<float4*>(&a_s[r*128 + cs]) =
            *reinterpret_cast<const float4*>(&g_hV[grow_s[r]*128 + cs]);
    stage_mat128(w_s, Wk2, t, 512);
    __syncthreads();
    tile_fma(a_s, w_s, n0, c0, acc2);
    __syncthreads();
    stage_mat128(w_s, Wv + 128*128, t, 512);  // Wv rows [128:256)
    __syncthreads();
    tile_fma(a_s, w_s, n0, c0, accv);

    // write Vh
    #pragma unroll
    for (int r = 0; r < 4; ++r) {
        float4 o;
        o.x = accv[r][0].x; o.y = accv[r][0].y;
        o.z = accv[r][1].x; o.w = accv[r][1].y;
        *reinterpret_cast<float4*>(&g_Vh[(base + n0 + r)*128 + c0]) = o;
    }

    // logits: reduce Q*k1*k2 over the 32 dims of each head (8 lanes x 4 cols)
    #pragma unroll
    for (int r = 0; r < 4; ++r) {
        int e = base + n0 + r;
        int node = e / KK;
        int k = e - node * KK;
        float4 q = *reinterpret_cast<const float4*>(&g_Q[node*128 + c0]);
        float p = q.x * acc1[r][0].x * acc2[r][0].x
                + q.y * acc1[r][0].y * acc2[r][0].y
                + q.z * acc1[r][1].x * acc2[r][1].x
                + q.w * acc1[r][1].y * acc2[r][1].y;
        p += __shfl_xor_sync(0xffffffffu, p, 1);
        p += __shfl_xor_sync(0xffffffffu, p, 2);
        p += __shfl_xor_sync(0xffffffffu, p, 4);
        if ((tx & 7) == 0)
            g_logits[(node*NHD + (tx >> 3))*KK + k] = p * (1.0f / 32.0f);
    }
}

// =====================================================================
// Kernel: per node: masked softmax over K per head, upd = attend*Vh,
//         dh = upd @ Wo, h_V = mask * LN(h_V + dh).   32 nodes / CTA.
// =====================================================================
__global__ __launch_bounds__(256) void k_attn(const int* __restrict__ E_idx,
                                              const float* __restrict__ mask,
                                              const float* __restrict__ Wo,
                                              const float* __restrict__ lng,
                                              const float* __restrict__ lnb) {
    extern __shared__ float sm[];
    float* w_s = sm;              // 128*128
    float* a_s = sm + 128*128;    // 32*128 (upd rows)
    __shared__ float att_s[32*NHD*KK];
    int t = threadIdx.x, tx = t & 31, ty = t >> 5;
    int n0 = ty * 4, c0 = tx * 4;
    int base = blockIdx.x * 32;

    // ---- softmax: one thread per (node, head) ----
    if (t < 128) {
        int nn = t >> 2, h = t & 3;
        int node = base + nn;
        int b = node / LL;
        float msel = mask[node];
        const int* eidx = &E_idx[node*KK];
        const float* lg = &g_logits[(node*NHD + h)*KK];
        float mk[KK], lv[KK];
        float mx = -3.4e38f;
        #pragma unroll
        for (int k = 0; k < KK; ++k) {
            int gi = b * LL + eidx[k];
            mk[k] = msel * mask[gi];
            lv[k] = lg[k];
            if (mk[k] > 0.f && lv[k] > mx) mx = lv[k];
        }
        float s = 0.f;
        #pragma unroll
        for (int k = 0; k < KK; ++k) {
            float e = (mk[k] > 0.f) ? __expf(lv[k] - mx) : 0.f;
            lv[k] = e; s += e;
        }
        float inv = (s > 0.f) ? (1.f / s) : 0.f;
        #pragma unroll
        for (int k = 0; k < KK; ++k)
            att_s[nn*(NHD*KK) + h*KK + k] = mk[k] * lv[k] * inv;
    }
    __syncthreads();

    // ---- upd rows into a_s ----
    #pragma unroll
    for (int r = 0; r < 4; ++r) {
        int nn = n0 + r;
        float4 u = make_float4(0.f, 0.f, 0.f, 0.f);
        const float* vh = &g_Vh[(long)(base + nn)*KK*128 + c0];
        const float* at = &att_s[nn*(NHD*KK) + (tx >> 3)*KK];
        #pragma unroll 6
        for (int k = 0; k < KK; ++k) {
            float a = at[k];
            float4 v = *reinterpret_cast<const float4*>(&vh[k*128]);
            u.x += a * v.x; u.y += a * v.y; u.z += a * v.z; u.w += a * v.w;
        }
        *reinterpret_cast<float4*>(&a_s[nn*128 + c0]) = u;
    }
    stage_mat128(w_s, Wo, t, 256);
    __syncthreads();

    float2 acc[4][2] = {};
    tile_fma(a_s, w_s, n0, c0, acc);

    // ---- residual + LayerNorm (ddof=1) + mask, in-place h_V update ----
    float4 gv  = *reinterpret_cast<const float4*>(&lng[c0]);
    float4 bv2 = *reinterpret_cast<const float4*>(&lnb[c0]);
    #pragma unroll
    for (int r = 0; r < 4; ++r) {
        int node = base + n0 + r;
        float4 hv = *reinterpret_cast<const float4*>(&g_hV[node*128 + c0]);
        float x0 = hv.x + acc[r][0].x, x1 = hv.y + acc[r][0].y;
        float x2 = hv.z + acc[r][1].x, x3 = hv.w + acc[r][1].y;
        float s  = x0 + x1 + x2 + x3;
        float s2 = x0*x0 + x1*x1 + x2*x2 + x3*x3;
        #pragma unroll
        for (int o = 16; o > 0; o >>= 1) {
            s  += __shfl_xor_sync(0xffffffffu, s,  o);
            s2 += __shfl_xor_sync(0xffffffffu, s2, o);
        }
        float mu  = s * (1.f / 128.f);
        float var = fmaxf((s2 - 128.f * mu * mu) * (1.f / 127.f), 0.f);
        float rs  = 1.f / (sqrtf(var + EPSX) + EPSX);
        float m   = mask[node];
        float4 o4;
        o4.x = m * (gv.x * (x0 - mu) * rs + bv2.x);
        o4.y = m * (gv.y * (x1 - mu) * rs + bv2.y);
        o4.z = m * (gv.z * (x2 - mu) * rs + bv2.z);
        o4.w = m * (gv.w * (x3 - mu) * rs + bv2.w);
        *reinterpret_cast<float4*>(&g_hV[node*128 + c0]) = o4;
    }
}

// =====================================================================
// Kernel: per edge row: h_E = LN(relu([hE, hV_gather, hV_self] @ fc1 + b))
// 64 rows / CTA, 3 input chunks of 128, in-place on g_hE.
// =====================================================================
__global__ __launch_bounds__(512) void k_edge_up(const int* __restrict__ E_idx,
                                                 const float* __restrict__ fc1w,
                                                 const float* __restrict__ fc1b,
                                                 const float* __restrict__ ng,
                                                 const float* __restrict__ nb) {
    extern __shared__ float sm[];
    float* w_s = sm;
    float* a_s = sm + 128*128;
    __shared__ int grow_s[64];
    int t = threadIdx.x, tx = t & 31, ty = t >> 5;
    int n0 = ty * 4, c0 = tx * 4, cs = tx * 4;
    int base = blockIdx.x * 64;

    if (t < 64) {
        int e = base + t;
        int b = e / (LL * KK);
        grow_s[t] = b * LL + E_idx[e];
    }

    float2 acc[4][2] = {};

    // chunk 0: h_E rows (own rows)
    for (int r = ty; r < 64; r += 16)
        *reinterpret_cast<float4*>(&a_s[r*128 + cs]) =
            *reinterpret_cast<const float4*>(&g_hE[(base + r)*128 + cs]);
    stage_mat128(w_s, fc1w, t, 512);
    __syncthreads();
    tile_fma(a_s, w_s, n0, c0, acc);
    __syncthreads();

    // chunk 1: gathered h_V rows
    for (int r = ty; r < 64; r += 16)
        *reinterpret_cast<float4*>(&a_s[r*128 + cs]) =
            *reinterpret_cast<const float4*>(&g_hV[grow_s[r]*128 + cs]);
    stage_mat128(w_s, fc1w + 128*128, t, 512);
    __syncthreads();
    tile_fma(a_s, w_s, n0, c0, acc);
    __syncthreads();

    // chunk 2: self h_V rows
    for (int r = ty; r < 64; r += 16) {
        int node = (base + r) / KK;
        *reinterpret_cast<float4*>(&a_s[r*128 + cs]) =
            *reinterpret_cast<const float4*>(&g_hV[node*128 + cs]);
    }
    stage_mat128(w_s, fc1w + 2*128*128, t, 512);
    __syncthreads();
    tile_fma(a_s, w_s, n0, c0, acc);

    // bias + relu + LayerNorm(norm_g, norm_b), write back in place
    float4 bb  = *reinterpret_cast<const float4*>(&fc1b[c0]);
    float4 gg  = *reinterpret_cast<const float4*>(&ng[c0]);
    float4 nbv = *reinterpret_cast<const float4*>(&nb[c0]);
    #pragma unroll
    for (int r = 0; r < 4; ++r) {
        float x0 = fmaxf(acc[r][0].x + bb.x, 0.f);
        float x1 = fmaxf(acc[r][0].y + bb.y, 0.f);
        float x2 = fmaxf(acc[r][1].x + bb.z, 0.f);
        float x3 = fmaxf(acc[r][1].y + bb.w, 0.f);
        float s  = x0 + x1 + x2 + x3;
        float s2 = x0*x0 + x1*x1 + x2*x2 + x3*x3;
        #pragma unroll
        for (int o = 16; o > 0; o >>= 1) {
            s  += __shfl_xor_sync(0xffffffffu, s,  o);
            s2 += __shfl_xor_sync(0xffffffffu, s2, o);
        }
        float mu  = s * (1.f / 128.f);
        float var = fmaxf((s2 - 128.f * mu * mu) * (1.f / 127.f), 0.f);
        float rs  = 1.f / (sqrtf(var + EPSX) + EPSX);
        float4 o4;
        o4.x = gg.x * (x0 - mu) * rs + nbv.x;
        o4.y = gg.y * (x1 - mu) * rs + nbv.y;
        o4.z = gg.z * (x2 - mu) * rs + nbv.z;
        o4.w = gg.w * (x3 - mu) * rs + nbv.w;
        *reinterpret_cast<float4*>(&g_hE[(base + n0 + r)*128 + c0]) = o4;
    }
}

__global__ void k_copy(float* __restrict__ out) {
    int i = blockIdx.x * blockDim.x + threadIdx.x;
    reinterpret_cast<float4*>(out)[i] = reinterpret_cast<const float4*>(g_hV)[i];
}

// =====================================================================
extern "C" void kernel_launch(void* const* d_in, const int* in_sizes, int n_in,
                              void* d_out, int out_size) {
    const float* V      = (const float*)d_in[0];
    const float* E      = (const float*)d_in[1];
    const int*   E_idx  = (const int*)  d_in[2];
    const float* mask   = (const float*)d_in[3];
    const float* Ws_w   = (const float*)d_in[4];
    const float* Ws_b   = (const float*)d_in[5];
    const float* Wt_w   = (const float*)d_in[6];
    const float* Wt_b   = (const float*)d_in[7];
    const float* Wq     = (const float*)d_in[8];
    const float* Wk1    = (const float*)d_in[9];
    const float* Wk2    = (const float*)d_in[10];
    const float* Wv     = (const float*)d_in[11];
    const float* Wo     = (const float*)d_in[12];
    const float* ln_g   = (const float*)d_in[13];
    const float* ln_b   = (const float*)d_in[14];
    const float* fc1_w  = (const float*)d_in[15];
    const float* fc1_b  = (const float*)d_in[16];
    const float* norm_g = (const float*)d_in[17];
    const float* norm_b = (const float*)d_in[18];

    const int SMG = (128*128 + 64*128) * 4;   // 98304 B
    const int SMA = (128*128 + 32*128) * 4;   // 81920 B
    cudaFuncSetAttribute(k_rowgemm,   cudaFuncAttributeMaxDynamicSharedMemorySize, SMG);
    cudaFuncSetAttribute(k_logits_vh, cudaFuncAttributeMaxDynamicSharedMemorySize, SMG);
    cudaFuncSetAttribute(k_attn,      cudaFuncAttributeMaxDynamicSharedMemorySize, SMA);
    cudaFuncSetAttribute(k_edge_up,   cudaFuncAttributeMaxDynamicSharedMemorySize, SMG);

    void *phV = nullptr, *pQ = nullptr, *phE = nullptr;
    cudaGetSymbolAddress(&phV, g_hV);
    cudaGetSymbolAddress(&pQ,  g_Q);
    cudaGetSymbolAddress(&phE, g_hE);

    // init projections
    k_rowgemm<<<NNODE/64, 512, SMG>>>(V, Ws_w, Ws_b, (float*)phV);
    k_rowgemm<<<NE/64,    512, SMG>>>(E, Wt_w, Wt_b, (float*)phE);

    for (int i = 0; i < NLAY; ++i) {
        k_rowgemm<<<NNODE/64, 512, SMG>>>((const float*)phV, Wq + i*128*128,
                                          nullptr, (float*)pQ);
        k_logits_vh<<<NE/64, 512, SMG>>>(E_idx, Wk1 + i*128*128,
                                         Wk2 + i*128*128, Wv + i*2*128*128);
        k_attn<<<NNODE/32, 256, SMA>>>(E_idx, mask, Wo + i*128*128,
                                       ln_g + i*128, ln_b + i*128);
        k_edge_up<<<NE/64, 512, SMG>>>(E_idx, fc1_w, fc1_b, norm_g, norm_b);
    }

    k_copy<<<(NNODE*HID/4)/256, 256>>>((float*)d_out);
    (void)in_sizes; (void)n_in; (void)out_size;
}